// round 8
// baseline (speedup 1.0000x reference)
#include <cuda_runtime.h>
#include <cstdint>

#define XS 128
#define BATCH 8
#define GRID_ELEMS (BATCH * XS * XS * XS)   // 16,777,216 floats = 67 MB (fits L2)

// Zero-initialized at module load (BSS). INVARIANT: every kernel_launch call
// leaves this array fully zeroed (reduce zeroes interior, boundary kernel
// zeroes chunk-boundary voxels), so no standalone 67MB zero pass is needed.
__device__ __align__(128) float g_grid[GRID_ELEMS];

// ---------------------------------------------------------------------------
// Kernel 1: scatter-add, 4 points per thread. Also zeroes the 16 outputs.
// ---------------------------------------------------------------------------
__global__ void scatter_kernel(const int4* __restrict__ idx4,
                               const float4* __restrict__ val4,
                               float* __restrict__ d_out, int out_size) {
    int t = blockIdx.x * blockDim.x + threadIdx.x;   // 0 .. 524287
    if (blockIdx.x == 0 && threadIdx.x < 16 && threadIdx.x < out_size)
        d_out[threadIdx.x] = 0.f;
    int b = t >> 16;                                 // 65536 threads per batch
    int4 a = __ldcs(idx4 + 3 * t);                   // x0 y0 z0 x1
    int4 c = __ldcs(idx4 + 3 * t + 1);               // y1 z1 x2 y2
    int4 e = __ldcs(idx4 + 3 * t + 2);               // z2 x3 y3 z3
    float4 v = __ldcs(val4 + t);
    float* gb = g_grid + (b << 21);
    atomicAdd(gb + ((a.x << 14) | (a.y << 7) | a.z), v.x);
    atomicAdd(gb + ((a.w << 14) | (c.x << 7) | c.y), v.y);
    atomicAdd(gb + ((c.z << 14) | (c.w << 7) | e.x), v.z);
    atomicAdd(gb + ((e.y << 14) | (e.z << 7) | e.w), v.w);
}

// ---------------------------------------------------------------------------
// Packed f32x2 diff accumulator: 4 diffs of (a - b) -> tv halves + packed mse.
// ---------------------------------------------------------------------------
__device__ __forceinline__ void acc4(const float4 a, const float4 bv,
                                     unsigned long long neg1,
                                     float& tv0, float& tv1,
                                     unsigned long long& m2a,
                                     unsigned long long& m2b) {
    unsigned long long axy, azw, bxy, bzw, d0, d1;
    asm("mov.b64 %0, {%1,%2};" : "=l"(axy) : "f"(a.x),  "f"(a.y));
    asm("mov.b64 %0, {%1,%2};" : "=l"(azw) : "f"(a.z),  "f"(a.w));
    asm("mov.b64 %0, {%1,%2};" : "=l"(bxy) : "f"(bv.x), "f"(bv.y));
    asm("mov.b64 %0, {%1,%2};" : "=l"(bzw) : "f"(bv.z), "f"(bv.w));
    asm("fma.rn.f32x2 %0, %1, %2, %3;" : "=l"(d0) : "l"(bxy), "l"(neg1), "l"(axy));
    asm("fma.rn.f32x2 %0, %1, %2, %3;" : "=l"(d1) : "l"(bzw), "l"(neg1), "l"(azw));
    asm("fma.rn.f32x2 %0, %1, %1, %0;" : "+l"(m2a) : "l"(d0));
    asm("fma.rn.f32x2 %0, %1, %1, %0;" : "+l"(m2b) : "l"(d1));
    float e0, e1, e2, e3;
    asm("mov.b64 {%0,%1}, %2;" : "=f"(e0), "=f"(e1) : "l"(d0));
    asm("mov.b64 {%0,%1}, %2;" : "=f"(e2), "=f"(e3) : "l"(d1));
    tv0 += fabsf(e0); tv1 += fabsf(e1);
    tv0 += fabsf(e2); tv1 += fabsf(e3);
}

// ---------------------------------------------------------------------------
// Kernel 2: fused TV + MSE reduction WITH read-and-zero.
// Block = 256 thr = 8 j-rows x 32 z-quads, 16 owned i-planes (+1 x-halo).
// Each owned voxel is gmem-LDG'd exactly once (by its owner thread);
// in-block consumers get it via smem (y) / shfl (z-seam) / register (x).
// Owner zeroes its voxel right after loading UNLESS it is on a chunk
// boundary (i%16==0 or j%8==0) that a neighbor block halo-reads — those
// are zeroed by boundary_zero_kernel afterwards.
// Grid: 8 b x 16 jc x 8 ic = 1024 blocks.
// ---------------------------------------------------------------------------
__global__ void reduce_zero_kernel(float* __restrict__ d_out) {
    __shared__ float4 sb[2][256];
    __shared__ float stv[8], smse[8];

    int tid = threadIdx.x;
    int k4  = tid & 31;          // z quad == lane
    int jl  = tid >> 5;          // warp id = local j
    int bx  = blockIdx.x;
    int b   = bx >> 7;
    int jc  = (bx >> 3) & 15;
    int ic  = bx & 7;
    int i0  = ic << 4;
    int j   = (jc << 3) + jl;

    float* colp = g_grid + ((size_t)b << 21) + (j << 7) + (k4 << 2);
    bool top    = (jl == 7);
    bool have_y = (!top) || (j < 127);
    const float4 z4 = make_float4(0.f, 0.f, 0.f, 0.f);

    unsigned long long neg1;
    asm("mov.b64 %0, {%1,%2};" : "=l"(neg1) : "f"(-1.0f), "f"(-1.0f));

    float tv0 = 0.f, tv1 = 0.f, mse_s = 0.f;
    unsigned long long m2a = 0ull, m2b = 0ull;
    float4 prev = z4;

    #pragma unroll 1
    for (int ii = 0; ii <= 16; ii++) {
        int i = i0 + ii;
        if (i > 127) break;                      // uniform (only ic==7, ii==16)
        float* p = colp + ((size_t)i << 14);
        float4 g = *reinterpret_cast<const float4*>(p);
        // read-and-zero: safe immediately — in-block consumers use smem copy
        if ((ii >= 1) & (ii <= 15) & (jl >= 1))
            *reinterpret_cast<float4*>(p) = z4;

        if (ii > 0)                              // x-diffs (planes i-1, i)
            acc4(g, prev, neg1, tv0, tv1, m2a, m2b);
        prev = g;

        if (ii < 16) {                           // owned plane: y + z diffs
            float4* s = sb[ii & 1];
            s[tid] = g;
            float nx = __shfl_down_sync(0xffffffffu, g.x, 1);   // z-seam
            float4 yn = z4;
            if (top & have_y)                    // y-halo row (foreign j%8==0)
                yn = *reinterpret_cast<const float4*>(p + 128);
            __syncthreads();

            float d;
            d = g.y - g.x; tv0 += fabsf(d); mse_s = fmaf(d, d, mse_s);
            d = g.z - g.y; tv1 += fabsf(d); mse_s = fmaf(d, d, mse_s);
            d = g.w - g.z; tv0 += fabsf(d); mse_s = fmaf(d, d, mse_s);
            if (k4 < 31) {
                d = nx - g.w; tv1 += fabsf(d); mse_s = fmaf(d, d, mse_s);
            }
            if (!top) yn = s[tid + 32];
            if (have_y) acc4(yn, g, neg1, tv0, tv1, m2a, m2b);
        }
    }

    float ma0, ma1, mb0, mb1;
    asm("mov.b64 {%0,%1}, %2;" : "=f"(ma0), "=f"(ma1) : "l"(m2a));
    asm("mov.b64 {%0,%1}, %2;" : "=f"(mb0), "=f"(mb1) : "l"(m2b));
    float tv  = tv0 + tv1;
    float mse = mse_s + (ma0 + ma1) + (mb0 + mb1);

    #pragma unroll
    for (int o = 16; o; o >>= 1) {
        tv  += __shfl_down_sync(0xffffffffu, tv,  o);
        mse += __shfl_down_sync(0xffffffffu, mse, o);
    }
    int lane = tid & 31, w = tid >> 5;
    if (lane == 0) { stv[w] = tv; smse[w] = mse; }
    __syncthreads();
    if (tid == 0) {
        float TV = 0.f, MS = 0.f;
        #pragma unroll
        for (int q = 0; q < 8; q++) { TV += stv[q]; MS += smse[q]; }
        const float inv_tv  = 1.f / 2097152.f;   // xsize^3
        const float inv_mse = 1.f / 32512.f;     // 2*128*128 - 2*128
        atomicAdd(&d_out[b],     TV * inv_tv);
        atomicAdd(&d_out[8 + b], MS * inv_mse);
    }
}

// ---------------------------------------------------------------------------
// Kernel 3: zero the chunk-boundary voxels (i%16==0 || j%8==0), ~11.5 MB.
// blockIdx.y = batch; 368 blocks x 256 thr = 94208 float4 stores per batch:
//   part A: 8 planes (i%16==0)  -> 8*4096 = 32768 float4
//   part B: 120 i x 16 j (j%8==0) x 32 k4 = 61440 float4
// ---------------------------------------------------------------------------
__global__ void boundary_zero_kernel() {
    int t = blockIdx.x * 256 + threadIdx.x;      // 0 .. 94207
    float4 z = make_float4(0.f, 0.f, 0.f, 0.f);
    float4* gb = reinterpret_cast<float4*>(g_grid) + ((size_t)blockIdx.y << 19);
    if (t < 32768) {
        int p = t >> 12;                         // plane 0..7 -> i = 16p
        int r = t & 4095;                        // j*32 + k4
        gb[(p << 16) + r] = z;                   // i*4096 = p*65536
    } else {
        int u   = t - 32768;                     // 0 .. 61439
        int k4v = u & 31;
        int j16 = (u >> 5) & 15;                 // j = 8*j16
        int q   = u >> 9;                        // 0 .. 119
        int i   = q + q / 15 + 1;                // 120 values skipping i%16==0
        gb[(i << 12) + (j16 << 8) + k4v] = z;    // i*4096 + j*32 + k4
    }
}

// ---------------------------------------------------------------------------
extern "C" void kernel_launch(void* const* d_in, const int* in_sizes, int n_in,
                              void* d_out, int out_size) {
    const int4*   idx4 = (const int4*)d_in[0];    // [B, N, 3] int32
    const float4* val4 = (const float4*)d_in[1];  // [B, N] float32
    float* out = (float*)d_out;                   // tv[8] ++ mse[8]

    scatter_kernel<<<2048, 256>>>(idx4, val4, out, out_size);
    reduce_zero_kernel<<<1024, 256>>>(out);
    boundary_zero_kernel<<<dim3(368, 8), 256>>>();
}

// round 9
// speedup vs baseline: 3.1441x; 3.1441x over previous
#include <cuda_runtime.h>
#include <cstdint>

#define XS 128
#define BATCH 8
#define GRID_ELEMS (BATCH * XS * XS * XS)   // 16,777,216 floats = 67 MB (fits L2)

__device__ __align__(128) float g_grid[GRID_ELEMS];

// ---------------------------------------------------------------------------
// Kernel 1: zero the grid with L2-only stores (st.global.cg) + zero outputs.
// Writes allocate dirty L2 lines -> scatter atomics stay L2-local.
// ---------------------------------------------------------------------------
__global__ void zero_kernel(float* __restrict__ d_out, int out_size) {
    int t = blockIdx.x * blockDim.x + threadIdx.x;   // 0 .. 2097151
    float4 z = make_float4(0.f, 0.f, 0.f, 0.f);
    float4* g4 = reinterpret_cast<float4*>(g_grid);
    __stcg(g4 + t, z);
    __stcg(g4 + t + 2097152, z);
    if (t < 16 && t < out_size) d_out[t] = 0.f;
}

// ---------------------------------------------------------------------------
// Kernel 2: scatter-add, 4 points per thread.
// 12 ints per 4 points -> 3x int4, values -> 1x float4.
// __ldcs: stream indices/values through L2 without evicting the grid.
// ---------------------------------------------------------------------------
__global__ void scatter_kernel(const int4* __restrict__ idx4,
                               const float4* __restrict__ val4) {
    int t = blockIdx.x * blockDim.x + threadIdx.x;   // 0 .. 524287
    int b = t >> 16;                                 // 65536 threads per batch
    int4 a = __ldcs(idx4 + 3 * t);                   // x0 y0 z0 x1
    int4 c = __ldcs(idx4 + 3 * t + 1);               // y1 z1 x2 y2
    int4 e = __ldcs(idx4 + 3 * t + 2);               // z2 x3 y3 z3
    float4 v = __ldcs(val4 + t);
    float* gb = g_grid + (b << 21);
    atomicAdd(gb + ((a.x << 14) | (a.y << 7) | a.z), v.x);
    atomicAdd(gb + ((a.w << 14) | (c.x << 7) | c.y), v.y);
    atomicAdd(gb + ((c.z << 14) | (c.w << 7) | e.x), v.z);
    atomicAdd(gb + ((e.y << 14) | (e.z << 7) | e.w), v.w);
}

// ---------------------------------------------------------------------------
// Packed f32x2 diff accumulator: 4 diffs of (a - b) -> tv halves + packed mse.
// Sign of the diff is irrelevant for |d| and d*d, so d = fma(b, -1, a).
// ---------------------------------------------------------------------------
__device__ __forceinline__ void acc4(const float4 a, const float4 bv,
                                     unsigned long long neg1,
                                     float& tv0, float& tv1,
                                     unsigned long long& m2a,
                                     unsigned long long& m2b) {
    unsigned long long axy, azw, bxy, bzw, d0, d1;
    asm("mov.b64 %0, {%1,%2};" : "=l"(axy) : "f"(a.x),  "f"(a.y));
    asm("mov.b64 %0, {%1,%2};" : "=l"(azw) : "f"(a.z),  "f"(a.w));
    asm("mov.b64 %0, {%1,%2};" : "=l"(bxy) : "f"(bv.x), "f"(bv.y));
    asm("mov.b64 %0, {%1,%2};" : "=l"(bzw) : "f"(bv.z), "f"(bv.w));
    asm("fma.rn.f32x2 %0, %1, %2, %3;" : "=l"(d0) : "l"(bxy), "l"(neg1), "l"(axy));
    asm("fma.rn.f32x2 %0, %1, %2, %3;" : "=l"(d1) : "l"(bzw), "l"(neg1), "l"(azw));
    asm("fma.rn.f32x2 %0, %1, %1, %0;" : "+l"(m2a) : "l"(d0));
    asm("fma.rn.f32x2 %0, %1, %1, %0;" : "+l"(m2b) : "l"(d1));
    float e0, e1, e2, e3;
    asm("mov.b64 {%0,%1}, %2;" : "=f"(e0), "=f"(e1) : "l"(d0));
    asm("mov.b64 {%0,%1}, %2;" : "=f"(e2), "=f"(e3) : "l"(d1));
    tv0 += fabsf(e0); tv1 += fabsf(e1);
    tv0 += fabsf(e2); tv1 += fabsf(e3);
}

// ---------------------------------------------------------------------------
// Kernel 3: fused TV + MSE reduction. 8-wide z strips, predicate-free edges.
// Block = 128 thr = 16 z-slots x 8 j-rows. 16 owned i-planes + clamped halo.
// x-diffs: register chain (clamp i=127 -> diff 0). y-diffs: direct LDG of
// row j+1 (clamp j=127 -> self -> diff 0; L1 hit for 7/8 warps). z: shifted
// packed vectors + shfl seam (zs==15 clamped to self -> diff 0).
// Grid: 8 b x 16 jc x 8 ic = 1024 blocks. No __syncthreads in the loop.
// ---------------------------------------------------------------------------
__global__ void reduce_kernel(float* __restrict__ d_out) {
    __shared__ float stv[4], smse[4];

    int tid = threadIdx.x;
    int zs  = tid & 15;          // z slot: z = 8*zs .. 8*zs+7
    int jl  = tid >> 4;          // 0..7 local j
    int bx  = blockIdx.x;
    int b   = bx >> 7;
    int jc  = (bx >> 3) & 15;
    int ic  = bx & 7;
    int i0  = ic << 4;
    int j   = (jc << 3) + jl;

    const float* colp = g_grid + ((size_t)b << 21) + (j << 7) + (zs << 3);
    // y-neighbor column: row j+1, clamped at the global edge (diffs -> 0)
    const float* coly = (j < 127) ? colp + 128 : colp;
    bool zseam = (zs < 15);

    unsigned long long neg1;
    asm("mov.b64 %0, {%1,%2};" : "=l"(neg1) : "f"(-1.0f), "f"(-1.0f));

    float tv0 = 0.f, tv1 = 0.f;
    unsigned long long m2a = 0ull, m2b = 0ull;

    float4 c0 = *reinterpret_cast<const float4*>(colp + ((size_t)i0 << 14));
    float4 c1 = *reinterpret_cast<const float4*>(colp + ((size_t)i0 << 14) + 4);
    float4 y0 = *reinterpret_cast<const float4*>(coly + ((size_t)i0 << 14));
    float4 y1 = *reinterpret_cast<const float4*>(coly + ((size_t)i0 << 14) + 4);

    #pragma unroll 4
    for (int ii = 0; ii < 16; ii++) {
        int inext  = i0 + ii + 1;
        int iclamp = (inext <= 127) ? inext : 127;   // clamp -> x-diff 0
        size_t off = (size_t)iclamp << 14;
        float4 n0 = *reinterpret_cast<const float4*>(colp + off);
        float4 n1 = *reinterpret_cast<const float4*>(colp + off + 4);
        float4 w0 = *reinterpret_cast<const float4*>(coly + off);
        float4 w1 = *reinterpret_cast<const float4*>(coly + off + 4);

        // z-diffs: shifted vectors; seam from next z-slot (lane+1)
        float nx = __shfl_down_sync(0xffffffffu, c0.x, 1);
        if (!zseam) nx = c1.w;                       // clamp -> diff 0
        float4 s0 = make_float4(c0.y, c0.z, c0.w, c1.x);
        float4 s1 = make_float4(c1.y, c1.z, c1.w, nx);
        acc4(s0, c0, neg1, tv0, tv1, m2a, m2b);
        acc4(s1, c1, neg1, tv0, tv1, m2a, m2b);
        // y-diffs
        acc4(y0, c0, neg1, tv0, tv1, m2a, m2b);
        acc4(y1, c1, neg1, tv0, tv1, m2a, m2b);
        // x-diffs
        acc4(n0, c0, neg1, tv0, tv1, m2a, m2b);
        acc4(n1, c1, neg1, tv0, tv1, m2a, m2b);

        c0 = n0; c1 = n1; y0 = w0; y1 = w1;
    }

    float ma0, ma1, mb0, mb1;
    asm("mov.b64 {%0,%1}, %2;" : "=f"(ma0), "=f"(ma1) : "l"(m2a));
    asm("mov.b64 {%0,%1}, %2;" : "=f"(mb0), "=f"(mb1) : "l"(m2b));
    float tv  = tv0 + tv1;
    float mse = (ma0 + ma1) + (mb0 + mb1);

    // block reduction: warp shuffle -> shared -> single atomicAdd
    #pragma unroll
    for (int o = 16; o; o >>= 1) {
        tv  += __shfl_down_sync(0xffffffffu, tv,  o);
        mse += __shfl_down_sync(0xffffffffu, mse, o);
    }
    int lane = tid & 31, w = tid >> 5;
    if (lane == 0) { stv[w] = tv; smse[w] = mse; }
    __syncthreads();
    if (tid == 0) {
        float TV = stv[0] + stv[1] + stv[2] + stv[3];
        float MS = smse[0] + smse[1] + smse[2] + smse[3];
        const float inv_tv  = 1.f / 2097152.f;   // xsize^3
        const float inv_mse = 1.f / 32512.f;     // 2*128*128 - 2*128
        atomicAdd(&d_out[b],     TV * inv_tv);
        atomicAdd(&d_out[8 + b], MS * inv_mse);
    }
}

// ---------------------------------------------------------------------------
extern "C" void kernel_launch(void* const* d_in, const int* in_sizes, int n_in,
                              void* d_out, int out_size) {
    const int4*   idx4 = (const int4*)d_in[0];    // [B, N, 3] int32
    const float4* val4 = (const float4*)d_in[1];  // [B, N] float32
    float* out = (float*)d_out;                   // tv[8] ++ mse[8]

    zero_kernel<<<2048, 1024>>>(out, out_size);   // 2M threads x 2x stcg.128
    scatter_kernel<<<2048, 256>>>(idx4, val4);    // 524288 threads x 4 points
    reduce_kernel<<<1024, 128>>>(out);            // 8b x 16jc x 8ic strips
}

// round 10
// speedup vs baseline: 3.2390x; 1.0302x over previous
#include <cuda_runtime.h>
#include <cstdint>

#define XS 128
#define BATCH 8
#define GRID_ELEMS (BATCH * XS * XS * XS)   // 16,777,216 floats = 67 MB (fits L2)

__device__ __align__(128) float g_grid[GRID_ELEMS];

// ---------------------------------------------------------------------------
// Kernel 1: zero the grid (2x float4 per thread) + zero the 16 output accums.
// Triggers programmatic launch of the dependent scatter kernel at entry so
// scatter blocks can start loading their (independent) inputs while the
// zeroing drains.
// ---------------------------------------------------------------------------
__global__ void zero_kernel(float* __restrict__ d_out, int out_size) {
    cudaTriggerProgrammaticLaunchCompletion();
    int t = blockIdx.x * blockDim.x + threadIdx.x;   // 0 .. 2097151
    float4 z = make_float4(0.f, 0.f, 0.f, 0.f);
    float4* g4 = reinterpret_cast<float4*>(g_grid);
    g4[t]           = z;
    g4[t + 2097152] = z;
    if (t < 16 && t < out_size) d_out[t] = 0.f;
}

// ---------------------------------------------------------------------------
// Kernel 2: scatter-add, 4 points per thread, PDL-overlapped with zeroing.
// Input loads (indices/values — independent of the grid) issue BEFORE
// cudaGridDependencySynchronize(); atomics to the grid only after it.
// __ldcs: stream inputs through L2 without evicting the grid.
// ---------------------------------------------------------------------------
__global__ void scatter_kernel(const int4* __restrict__ idx4,
                               const float4* __restrict__ val4) {
    int t = blockIdx.x * blockDim.x + threadIdx.x;   // 0 .. 524287
    int b = t >> 16;                                 // 65536 threads per batch
    int4 a = __ldcs(idx4 + 3 * t);                   // x0 y0 z0 x1
    int4 c = __ldcs(idx4 + 3 * t + 1);               // y1 z1 x2 y2
    int4 e = __ldcs(idx4 + 3 * t + 2);               // z2 x3 y3 z3
    float4 v = __ldcs(val4 + t);

    cudaGridDependencySynchronize();                 // wait: grid fully zeroed

    float* gb = g_grid + (b << 21);
    atomicAdd(gb + ((a.x << 14) | (a.y << 7) | a.z), v.x);
    atomicAdd(gb + ((a.w << 14) | (c.x << 7) | c.y), v.y);
    atomicAdd(gb + ((c.z << 14) | (c.w << 7) | e.x), v.z);
    atomicAdd(gb + ((e.y << 14) | (e.z << 7) | e.w), v.w);
}

// ---------------------------------------------------------------------------
// Packed f32x2 diff accumulator: 4 diffs of (a - b) -> tv halves + packed mse.
// Sign of the diff is irrelevant for |d| and d*d, so d = fma(b, -1, a).
// ---------------------------------------------------------------------------
__device__ __forceinline__ void acc4(const float4 a, const float4 bv,
                                     unsigned long long neg1,
                                     float& tv0, float& tv1,
                                     unsigned long long& m2a,
                                     unsigned long long& m2b) {
    unsigned long long axy, azw, bxy, bzw, d0, d1;
    asm("mov.b64 %0, {%1,%2};" : "=l"(axy) : "f"(a.x),  "f"(a.y));
    asm("mov.b64 %0, {%1,%2};" : "=l"(azw) : "f"(a.z),  "f"(a.w));
    asm("mov.b64 %0, {%1,%2};" : "=l"(bxy) : "f"(bv.x), "f"(bv.y));
    asm("mov.b64 %0, {%1,%2};" : "=l"(bzw) : "f"(bv.z), "f"(bv.w));
    asm("fma.rn.f32x2 %0, %1, %2, %3;" : "=l"(d0) : "l"(bxy), "l"(neg1), "l"(axy));
    asm("fma.rn.f32x2 %0, %1, %2, %3;" : "=l"(d1) : "l"(bzw), "l"(neg1), "l"(azw));
    asm("fma.rn.f32x2 %0, %1, %1, %0;" : "+l"(m2a) : "l"(d0));
    asm("fma.rn.f32x2 %0, %1, %1, %0;" : "+l"(m2b) : "l"(d1));
    float e0, e1, e2, e3;
    asm("mov.b64 {%0,%1}, %2;" : "=f"(e0), "=f"(e1) : "l"(d0));
    asm("mov.b64 {%0,%1}, %2;" : "=f"(e2), "=f"(e3) : "l"(d1));
    tv0 += fabsf(e0); tv1 += fabsf(e1);
    tv0 += fabsf(e2); tv1 += fabsf(e3);
}

// ---------------------------------------------------------------------------
// Kernel 3: fused TV + MSE reduction. 8-wide z strips, predicate-free edges.
// Block = 128 thr = 16 z-slots x 8 j-rows. 16 owned i-planes + clamped halo.
// x-diffs: register chain (clamp i=127 -> diff 0). y-diffs: direct LDG of
// row j+1 (clamp j=127 -> self -> diff 0; L1 hit for 7/8 warps). z: shifted
// packed vectors + shfl seam (zs==15 clamped to self -> diff 0).
// Grid: 8 b x 16 jc x 8 ic = 1024 blocks. No __syncthreads in the loop.
// ---------------------------------------------------------------------------
__global__ void reduce_kernel(float* __restrict__ d_out) {
    __shared__ float stv[4], smse[4];

    int tid = threadIdx.x;
    int zs  = tid & 15;          // z slot: z = 8*zs .. 8*zs+7
    int jl  = tid >> 4;          // 0..7 local j
    int bx  = blockIdx.x;
    int b   = bx >> 7;
    int jc  = (bx >> 3) & 15;
    int ic  = bx & 7;
    int i0  = ic << 4;
    int j   = (jc << 3) + jl;

    const float* colp = g_grid + ((size_t)b << 21) + (j << 7) + (zs << 3);
    // y-neighbor column: row j+1, clamped at the global edge (diffs -> 0)
    const float* coly = (j < 127) ? colp + 128 : colp;
    bool zseam = (zs < 15);

    unsigned long long neg1;
    asm("mov.b64 %0, {%1,%2};" : "=l"(neg1) : "f"(-1.0f), "f"(-1.0f));

    float tv0 = 0.f, tv1 = 0.f;
    unsigned long long m2a = 0ull, m2b = 0ull;

    float4 c0 = *reinterpret_cast<const float4*>(colp + ((size_t)i0 << 14));
    float4 c1 = *reinterpret_cast<const float4*>(colp + ((size_t)i0 << 14) + 4);
    float4 y0 = *reinterpret_cast<const float4*>(coly + ((size_t)i0 << 14));
    float4 y1 = *reinterpret_cast<const float4*>(coly + ((size_t)i0 << 14) + 4);

    #pragma unroll 4
    for (int ii = 0; ii < 16; ii++) {
        int inext  = i0 + ii + 1;
        int iclamp = (inext <= 127) ? inext : 127;   // clamp -> x-diff 0
        size_t off = (size_t)iclamp << 14;
        float4 n0 = *reinterpret_cast<const float4*>(colp + off);
        float4 n1 = *reinterpret_cast<const float4*>(colp + off + 4);
        float4 w0 = *reinterpret_cast<const float4*>(coly + off);
        float4 w1 = *reinterpret_cast<const float4*>(coly + off + 4);

        // z-diffs: shifted vectors; seam from next z-slot (lane+1)
        float nx = __shfl_down_sync(0xffffffffu, c0.x, 1);
        if (!zseam) nx = c1.w;                       // clamp -> diff 0
        float4 s0 = make_float4(c0.y, c0.z, c0.w, c1.x);
        float4 s1 = make_float4(c1.y, c1.z, c1.w, nx);
        acc4(s0, c0, neg1, tv0, tv1, m2a, m2b);
        acc4(s1, c1, neg1, tv0, tv1, m2a, m2b);
        // y-diffs
        acc4(y0, c0, neg1, tv0, tv1, m2a, m2b);
        acc4(y1, c1, neg1, tv0, tv1, m2a, m2b);
        // x-diffs
        acc4(n0, c0, neg1, tv0, tv1, m2a, m2b);
        acc4(n1, c1, neg1, tv0, tv1, m2a, m2b);

        c0 = n0; c1 = n1; y0 = w0; y1 = w1;
    }

    float ma0, ma1, mb0, mb1;
    asm("mov.b64 {%0,%1}, %2;" : "=f"(ma0), "=f"(ma1) : "l"(m2a));
    asm("mov.b64 {%0,%1}, %2;" : "=f"(mb0), "=f"(mb1) : "l"(m2b));
    float tv  = tv0 + tv1;
    float mse = (ma0 + ma1) + (mb0 + mb1);

    // block reduction: warp shuffle -> shared -> single atomicAdd
    #pragma unroll
    for (int o = 16; o; o >>= 1) {
        tv  += __shfl_down_sync(0xffffffffu, tv,  o);
        mse += __shfl_down_sync(0xffffffffu, mse, o);
    }
    int lane = tid & 31, w = tid >> 5;
    if (lane == 0) { stv[w] = tv; smse[w] = mse; }
    __syncthreads();
    if (tid == 0) {
        float TV = stv[0] + stv[1] + stv[2] + stv[3];
        float MS = smse[0] + smse[1] + smse[2] + smse[3];
        const float inv_tv  = 1.f / 2097152.f;   // xsize^3
        const float inv_mse = 1.f / 32512.f;     // 2*128*128 - 2*128
        atomicAdd(&d_out[b],     TV * inv_tv);
        atomicAdd(&d_out[8 + b], MS * inv_mse);
    }
}

// ---------------------------------------------------------------------------
extern "C" void kernel_launch(void* const* d_in, const int* in_sizes, int n_in,
                              void* d_out, int out_size) {
    const int4*   idx4 = (const int4*)d_in[0];    // [B, N, 3] int32
    const float4* val4 = (const float4*)d_in[1];  // [B, N] float32
    float* out = (float*)d_out;                   // tv[8] ++ mse[8]

    zero_kernel<<<2048, 1024>>>(out, out_size);

    // Scatter with Programmatic Dependent Launch: launches while zero drains,
    // loads its inputs, then griddepsyncs before touching the grid.
    cudaLaunchConfig_t cfg = {};
    cfg.gridDim  = dim3(2048);
    cfg.blockDim = dim3(256);
    cfg.dynamicSmemBytes = 0;
    cfg.stream = 0;
    cudaLaunchAttribute at[1];
    at[0].id = cudaLaunchAttributeProgrammaticStreamSerialization;
    at[0].val.programmaticStreamSerializationAllowed = 1;
    cfg.attrs = at;
    cfg.numAttrs = 1;
    cudaLaunchKernelEx(&cfg, scatter_kernel, idx4, val4);

    reduce_kernel<<<1024, 128>>>(out);            // 8b x 16jc x 8ic strips
}